// round 2
// baseline (speedup 1.0000x reference)
#include <cuda_runtime.h>
#include <math.h>

#define BN 4
#define HH 128
#define WW 128
#define HWS (HH * WW)
#define CC 64
#define O1 64
#define O2 32
#define NOFF 27
#define NOFFP 28
#define SPLITC 4
#define CSLICE (CC / SPLITC)   // 16
#define KG 3
#define NPIX (BN * HWS)

// ---------------- device scratch ----------------
__device__ float g_x1[BN * CC * HWS];
__device__ float g_x2[BN * CC * HWS];
__device__ float g_off[BN * NOFF * HWS];
__device__ float g_offp[SPLITC][BN * NOFF * HWS];
__device__ float g_dp[KG][BN * O1 * HWS];
__device__ float g_wo1[CC * 9 * NOFFP];
__device__ float g_wo2[CC * 9 * NOFFP];
__device__ float g_wr1[9 * CC * O1];
__device__ float g_wr2[9 * CC * O2];
__device__ float g_b1[O1];
__device__ float g_b2[O2];

// ---------------- f32x2 packed helpers ----------------
__device__ __forceinline__ unsigned long long pack2(float a, float b) {
    unsigned long long r;
    asm("mov.b64 %0, {%1, %2};" : "=l"(r)
        : "r"(__float_as_uint(a)), "r"(__float_as_uint(b)));
    return r;
}
__device__ __forceinline__ void unpack2(unsigned long long v, float& a, float& b) {
    unsigned int x, y;
    asm("mov.b64 {%0, %1}, %2;" : "=r"(x), "=r"(y) : "l"(v));
    a = __uint_as_float(x); b = __uint_as_float(y);
}
#define FMA2(acc, a, b) asm("fma.rn.f32x2 %0, %1, %2, %0;" : "+l"(acc) : "l"(a), "l"(b))

// ---------------- prep: concat, weight reorder, BN fold ----------------
__global__ void prep_kernel(
    const float* __restrict__ pA, const float* __restrict__ pB,
    const float* __restrict__ wo1,
    const float* __restrict__ w1, const float* __restrict__ g1,
    const float* __restrict__ be1, const float* __restrict__ rm1, const float* __restrict__ rv1,
    const float* __restrict__ wo2,
    const float* __restrict__ w2, const float* __restrict__ g2,
    const float* __restrict__ be2, const float* __restrict__ rm2, const float* __restrict__ rv2)
{
    int t = blockIdx.x * blockDim.x + threadIdx.x;
    int stride = gridDim.x * blockDim.x;

    for (int i = t; i < BN * CC * HWS; i += stride) {
        int b = i / (CC * HWS);
        int r = i % (CC * HWS);
        int c = r / HWS;
        int s = r % HWS;
        g_x1[i] = (c < 32) ? pB[(b * 32 + c) * HWS + s]
                           : pA[(b * 32 + (c - 32)) * HWS + s];
    }

    // offset weights: g_wo[(c*9+k)*28 + o] = wo[(o*CC+c)*9 + k]
    for (int i = t; i < CC * 9 * NOFFP; i += stride) {
        int o = i % NOFFP;
        int ck = i / NOFFP;
        int k = ck % 9;
        int c = ck / 9;
        g_wo1[i] = (o < NOFF) ? wo1[(o * CC + c) * 9 + k] : 0.f;
        g_wo2[i] = (o < NOFF) ? wo2[(o * CC + c) * 9 + k] : 0.f;
    }

    // main weights: g_wr[(k*CC+c)*O + o] = w[(o*CC+c)*9 + k] * inv[o]
    for (int i = t; i < 9 * CC * O1; i += stride) {
        int o = i % O1;
        int kc = i / O1;
        int c = kc % CC;
        int k = kc / CC;
        float inv = g1[o] * rsqrtf(rv1[o] + 1e-5f);
        g_wr1[i] = w1[(o * CC + c) * 9 + k] * inv;
    }
    for (int i = t; i < 9 * CC * O2; i += stride) {
        int o = i % O2;
        int kc = i / O2;
        int c = kc % CC;
        int k = kc / CC;
        float inv = g2[o] * rsqrtf(rv2[o] + 1e-5f);
        g_wr2[i] = w2[(o * CC + c) * 9 + k] * inv;
    }
    if (t < O1) { float inv = g1[t] * rsqrtf(rv1[t] + 1e-5f); g_b1[t] = be1[t] - rm1[t] * inv; }
    if (t < O2) { float inv = g2[t] * rsqrtf(rv2[t] + 1e-5f); g_b2[t] = be2[t] - rm2[t] * inv; }
}

// ---------------- offset conv partial (c-slice) ----------------
__global__ __launch_bounds__(256, 3)
void offconv_kernel(const float* __restrict__ xin, const float* __restrict__ wo)
{
    __shared__ __align__(16) float sw[CSLICE * 9 * NOFFP];   // 16128 B
    int cg = blockIdx.y;
    const float* wsrc = wo + cg * CSLICE * 9 * NOFFP;
    for (int i = threadIdx.x; i < CSLICE * 9 * NOFFP; i += 256) sw[i] = wsrc[i];
    __syncthreads();

    int t = blockIdx.x * 256 + threadIdx.x;
    int b = t / HWS;
    int s = t % HWS;
    int h = s / WW;
    int w = s % WW;

    unsigned long long acc2[NOFFP / 2];
#pragma unroll
    for (int j = 0; j < NOFFP / 2; j++) acc2[j] = 0ull;

    const float* xb = xin + (b * CC + cg * CSLICE) * HWS;
#pragma unroll 1
    for (int c = 0; c < CSLICE; c++) {
        const float* xc = xb + c * HWS;
        float v[9];
#pragma unroll
        for (int r = 0; r < 3; r++) {
            int y = h + r - 1;
#pragma unroll
            for (int q = 0; q < 3; q++) {
                int xx = w + q - 1;
                v[r * 3 + q] = (y >= 0 && y < HH && xx >= 0 && xx < WW) ? xc[y * WW + xx] : 0.f;
            }
        }
        const float* swc = sw + c * 9 * NOFFP;
#pragma unroll
        for (int k = 0; k < 9; k++) {
            unsigned long long vv = pack2(v[k], v[k]);
            const ulonglong2* wp = (const ulonglong2*)(swc + k * NOFFP);
#pragma unroll
            for (int j = 0; j < NOFFP / 4; j++) {   // 7
                ulonglong2 wq = wp[j];
                FMA2(acc2[2 * j], vv, wq.x);
                FMA2(acc2[2 * j + 1], vv, wq.y);
            }
        }
    }
    float* ob = g_offp[cg] + b * NOFF * HWS + s;
#pragma unroll
    for (int j = 0; j < NOFF / 2; j++) {   // 13 pairs: o 0..25
        float a, bb; unpack2(acc2[j], a, bb);
        ob[(2 * j) * HWS] = a;
        ob[(2 * j + 1) * HWS] = bb;
    }
    { float a, bb; unpack2(acc2[13], a, bb); ob[26 * HWS] = a; }
}

// ---------------- offset combine: sum partials + bias, pre-sigmoid masks ----------------
__global__ void off_combine(const float* __restrict__ bo)
{
    int i = blockIdx.x * 256 + threadIdx.x;
    if (i >= BN * NOFF * HWS) return;
    int o = (i / HWS) % NOFF;
    float s = g_offp[0][i] + g_offp[1][i] + g_offp[2][i] + g_offp[3][i] + bo[o];
    if (o >= 18) s = 1.f / (1.f + expf(-s));
    g_off[i] = s;
}

// ---------------- deform sample + partial einsum over a k-group ----------------
template <int O, int MINB>
__global__ __launch_bounds__(256, MINB)
void deform_kernel(const float* __restrict__ xin, const float* __restrict__ wr)
{
    extern __shared__ __align__(16) float sw[];   // 3*CC*O floats
    int kg = blockIdx.z;
    const float* wsrc = wr + kg * 3 * CC * O;
    for (int i = threadIdx.x; i < 3 * CC * O; i += 256) sw[i] = wsrc[i];
    __syncthreads();

    int t = blockIdx.x * 256 + threadIdx.x;
    int b = t / HWS;
    int s = t % HWS;
    int h = s / WW;
    int w = s % WW;

    const float* offp = g_off + b * NOFF * HWS + s;
    const float* xb = xin + b * CC * HWS;

    unsigned long long acc2[O / 2];
#pragma unroll
    for (int j = 0; j < O / 2; j++) acc2[j] = 0ull;

#pragma unroll 1
    for (int kk = 0; kk < 3; kk++) {
        int k = kg * 3 + kk;
        float dy = offp[(2 * k) * HWS];
        float dx = offp[(2 * k + 1) * HWS];
        float m  = offp[(18 + k) * HWS];   // pre-sigmoided

        float ys = (float)h + (float)(k / 3 - 1) + dy;
        float xs = (float)w + (float)(k % 3 - 1) + dx;
        float y0f = floorf(ys), x0f = floorf(xs);
        float fy = ys - y0f, fx = xs - x0f;
        int y0 = (int)y0f, x0 = (int)x0f;
        int y1 = y0 + 1, x1 = x0 + 1;

        float vy0 = (y0 >= 0 && y0 < HH) ? 1.f : 0.f;
        float vy1 = (y1 >= 0 && y1 < HH) ? 1.f : 0.f;
        float vx0 = (x0 >= 0 && x0 < WW) ? 1.f : 0.f;
        float vx1 = (x1 >= 0 && x1 < WW) ? 1.f : 0.f;

        float w00 = (1.f - fy) * (1.f - fx) * m * vy0 * vx0;
        float w01 = (1.f - fy) * fx * m * vy0 * vx1;
        float w10 = fy * (1.f - fx) * m * vy1 * vx0;
        float w11 = fy * fx * m * vy1 * vx1;

        int cy0 = min(max(y0, 0), HH - 1), cy1 = min(max(y1, 0), HH - 1);
        int cx0 = min(max(x0, 0), WW - 1), cx1 = min(max(x1, 0), WW - 1);
        int i00 = cy0 * WW + cx0, i01 = cy0 * WW + cx1;
        int i10 = cy1 * WW + cx0, i11 = cy1 * WW + cx1;

        const float* swk = sw + kk * CC * O;
#pragma unroll 2
        for (int c = 0; c < CC; c++) {
            const float* xc = xb + c * HWS;
            float val = w00 * xc[i00] + w01 * xc[i01] + w10 * xc[i10] + w11 * xc[i11];
            unsigned long long vv = pack2(val, val);
            const ulonglong2* wp = (const ulonglong2*)(swk + c * O);
#pragma unroll
            for (int j = 0; j < O / 4; j++) {
                ulonglong2 wq = wp[j];
                FMA2(acc2[2 * j], vv, wq.x);
                FMA2(acc2[2 * j + 1], vv, wq.y);
            }
        }
    }

    float* ob = g_dp[kg] + b * O * HWS + s;
#pragma unroll
    for (int j = 0; j < O / 2; j++) {
        float a, bb; unpack2(acc2[j], a, bb);
        ob[(2 * j) * HWS] = a;
        ob[(2 * j + 1) * HWS] = bb;
    }
}

// ---------------- deform combine: sum k-partials + bias, relu [, gate] ----------------
template <int O, bool GATE>
__global__ void d_combine(const float* __restrict__ bias, float* __restrict__ out,
                          const float* __restrict__ Aatt, const float* __restrict__ Batt)
{
    int i = blockIdx.x * 256 + threadIdx.x;
    if (i >= BN * O * HWS) return;
    int o = (i / HWS) % O;
    float v = g_dp[0][i] + g_dp[1][i] + g_dp[2][i] + bias[o];
    v = fmaxf(v, 0.f);
    if (GATE) {
        int b = i / (O * HWS);
        int s = i % HWS;
        v *= (1.f - Aatt[b * HWS + s]) * Batt[b * HWS + s];
    }
    out[i] = v;
}

// ---------------- launch ----------------
extern "C" void kernel_launch(void* const* d_in, const int* in_sizes, int n_in,
                              void* d_out, int out_size)
{
    const float* pA   = (const float*)d_in[1];
    const float* pB   = (const float*)d_in[2];
    const float* Aatt = (const float*)d_in[3];
    const float* Batt = (const float*)d_in[4];
    const float* wo1  = (const float*)d_in[5];
    const float* bo1  = (const float*)d_in[6];
    const float* w1   = (const float*)d_in[7];
    const float* g1   = (const float*)d_in[8];
    const float* be1  = (const float*)d_in[9];
    const float* rm1  = (const float*)d_in[10];
    const float* rv1  = (const float*)d_in[11];
    const float* wo2  = (const float*)d_in[12];
    const float* bo2  = (const float*)d_in[13];
    const float* w2   = (const float*)d_in[14];
    const float* g2   = (const float*)d_in[15];
    const float* be2  = (const float*)d_in[16];
    const float* rm2  = (const float*)d_in[17];
    const float* rv2  = (const float*)d_in[18];

    float *x1, *x2, *pwo1, *pwo2, *pwr1, *pwr2, *pb1, *pb2;
    cudaGetSymbolAddress((void**)&x1,   g_x1);
    cudaGetSymbolAddress((void**)&x2,   g_x2);
    cudaGetSymbolAddress((void**)&pwo1, g_wo1);
    cudaGetSymbolAddress((void**)&pwo2, g_wo2);
    cudaGetSymbolAddress((void**)&pwr1, g_wr1);
    cudaGetSymbolAddress((void**)&pwr2, g_wr2);
    cudaGetSymbolAddress((void**)&pb1,  g_b1);
    cudaGetSymbolAddress((void**)&pb2,  g_b2);

    const int smem_d1 = 3 * CC * O1 * 4;   // 49152
    const int smem_d2 = 3 * CC * O2 * 4;   // 24576
    cudaFuncSetAttribute(deform_kernel<O1, 2>, cudaFuncAttributeMaxDynamicSharedMemorySize, smem_d1);
    cudaFuncSetAttribute(deform_kernel<O2, 3>, cudaFuncAttributeMaxDynamicSharedMemorySize, smem_d2);

    dim3 blk(256);
    dim3 goff(NPIX / 256, SPLITC);
    dim3 gdef(NPIX / 256, 1, KG);
    int noffel = BN * NOFF * HWS;

    prep_kernel<<<256, 256>>>(pA, pB, wo1, w1, g1, be1, rm1, rv1,
                              wo2, w2, g2, be2, rm2, rv2);

    offconv_kernel<<<goff, blk>>>(x1, pwo1);
    off_combine<<<(noffel + 255) / 256, blk>>>(bo1);
    deform_kernel<O1, 2><<<gdef, blk, smem_d1>>>(x1, pwr1);
    d_combine<O1, false><<<(BN * O1 * HWS + 255) / 256, blk>>>(pb1, x2, nullptr, nullptr);

    offconv_kernel<<<goff, blk>>>(x2, pwo2);
    off_combine<<<(noffel + 255) / 256, blk>>>(bo2);
    deform_kernel<O2, 3><<<gdef, blk, smem_d2>>>(x2, pwr2);
    d_combine<O2, true><<<(BN * O2 * HWS + 255) / 256, blk>>>(pb2, (float*)d_out, Aatt, Batt);
}

// round 3
// speedup vs baseline: 1.3777x; 1.3777x over previous
#include <cuda_runtime.h>
#include <math.h>

#define BN 4
#define HH 128
#define WW 128
#define HWS (HH * WW)
#define CC 64
#define O1 64
#define O2 32
#define NOFF 27
#define NPIX (BN * HWS)
#define TP 128           // pixels per block (one image row)

// ---------------- device scratch ----------------
__device__ float g_x1[BN * CC * HWS];
__device__ float g_x2[BN * CC * HWS];
__device__ float g_off[BN * NOFF * HWS];
__device__ float g_wo1[9 * CC * 32];    // [k][c][o32], zero-padded o>=27
__device__ float g_wo2[9 * CC * 32];
__device__ float g_wr1[9 * CC * O1];    // [k][c][o], BN-folded
__device__ float g_wr2[9 * CC * O2];
__device__ float g_b1[O1];
__device__ float g_b2[O2];

// ---------------- prep: concat, weight reorder, BN fold ----------------
__global__ void prep_kernel(
    const float* __restrict__ pA, const float* __restrict__ pB,
    const float* __restrict__ wo1,
    const float* __restrict__ w1, const float* __restrict__ g1,
    const float* __restrict__ be1, const float* __restrict__ rm1, const float* __restrict__ rv1,
    const float* __restrict__ wo2,
    const float* __restrict__ w2, const float* __restrict__ g2,
    const float* __restrict__ be2, const float* __restrict__ rm2, const float* __restrict__ rv2)
{
    int t = blockIdx.x * blockDim.x + threadIdx.x;
    int stride = gridDim.x * blockDim.x;

    for (int i = t; i < BN * CC * HWS; i += stride) {
        int b = i / (CC * HWS);
        int r = i % (CC * HWS);
        int c = r / HWS;
        int s = r % HWS;
        g_x1[i] = (c < 32) ? pB[(b * 32 + c) * HWS + s]
                           : pA[(b * 32 + (c - 32)) * HWS + s];
    }

    // offset weights: [k][c][o32]
    for (int i = t; i < 9 * CC * 32; i += stride) {
        int o = i % 32;
        int kc = i / 32;
        int c = kc % CC;
        int k = kc / CC;
        g_wo1[i] = (o < NOFF) ? wo1[(o * CC + c) * 9 + k] : 0.f;
        g_wo2[i] = (o < NOFF) ? wo2[(o * CC + c) * 9 + k] : 0.f;
    }

    // main weights [k][c][o] with BN scale folded
    for (int i = t; i < 9 * CC * O1; i += stride) {
        int o = i % O1;
        int kc = i / O1;
        int c = kc % CC;
        int k = kc / CC;
        float inv = g1[o] * rsqrtf(rv1[o] + 1e-5f);
        g_wr1[i] = w1[(o * CC + c) * 9 + k] * inv;
    }
    for (int i = t; i < 9 * CC * O2; i += stride) {
        int o = i % O2;
        int kc = i / O2;
        int c = kc % CC;
        int k = kc / CC;
        float inv = g2[o] * rsqrtf(rv2[o] + 1e-5f);
        g_wr2[i] = w2[(o * CC + c) * 9 + k] * inv;
    }
    if (t < O1) { float inv = g1[t] * rsqrtf(rv1[t] + 1e-5f); g_b1[t] = be1[t] - rm1[t] * inv; }
    if (t < O2) { float inv = g2[t] * rsqrtf(rv2[t] + 1e-5f); g_b2[t] = be2[t] - rm2[t] * inv; }
}

// ---------------- fused smem-staged GEMM kernel ----------------
// MODE 0: offset conv (O=32 padded, write 27 chans, sigmoid on 18..26, +bias)
// MODE 1: deform conv, bias+relu -> out
// MODE 2: deform conv, bias+relu, *(1-Aatt)*Batt -> out
template <int O, int MODE>
__global__ __launch_bounds__(256, 3)
void gemm_kernel(const float* __restrict__ xin,   // [b][CC][HWS]
                 const float* __restrict__ wgt,   // [9][CC][O]
                 const float* __restrict__ bias,  // [O] (MODE0: [27])
                 float* __restrict__ out,
                 const float* __restrict__ offs,  // MODE>0: g_off
                 const float* __restrict__ Aatt,
                 const float* __restrict__ Batt)
{
    extern __shared__ __align__(16) float smem_[];
    float* sv  = smem_;                 // CC*TP
    float* wk  = sv + CC * TP;          // CC*O
    float* swt = wk + CC * O;           // 4*TP (deform)
    int*   sidx = (int*)(swt + 4 * TP); // 4*TP (deform)

    const int tid = threadIdx.x;
    const int sb  = blockIdx.x * TP;    // global pixel base
    const int b   = sb / HWS;
    const int sl  = sb % HWS;           // pixel base within image (row-aligned)
    const int h   = sl / WW;

    constexpr int TX = (O == 64) ? 16 : 32;   // pixel-dim threads
    constexpr int NG = TP / (TX * 4);         // float4 pixel groups/thread (2 or 1)
    const int tx = tid % TX;
    const int ty = tid / TX;                  // output group: o = ty*4 + j

    const float* xb = xin + b * CC * HWS;

    float4 acc[NG][4];
#pragma unroll
    for (int g = 0; g < NG; g++)
#pragma unroll
        for (int j = 0; j < 4; j++) acc[g][j] = make_float4(0.f, 0.f, 0.f, 0.f);

#pragma unroll 1
    for (int k = 0; k < 9; k++) {
        // ---- phase A (deform only): per-pixel bilinear idx + weights ----
        if (MODE > 0) {
            if (tid < TP) {
                int p = tid;
                const float* op = offs + b * NOFF * HWS + sl + p;
                float dy = op[(2 * k) * HWS];
                float dx = op[(2 * k + 1) * HWS];
                float m  = op[(18 + k) * HWS];     // pre-sigmoided

                float ys = (float)(h + (k / 3 - 1)) + dy;
                float xs = (float)(p + (k % 3 - 1)) + dx;
                float y0f = floorf(ys), x0f = floorf(xs);
                float fy = ys - y0f, fx = xs - x0f;
                int y0 = (int)y0f, x0 = (int)x0f;
                int y1 = y0 + 1, x1 = x0 + 1;

                float vy0 = (y0 >= 0 && y0 < HH) ? m : 0.f;
                float vy1 = (y1 >= 0 && y1 < HH) ? m : 0.f;
                float vx0 = (x0 >= 0 && x0 < WW) ? 1.f : 0.f;
                float vx1 = (x1 >= 0 && x1 < WW) ? 1.f : 0.f;

                swt[0 * TP + p] = (1.f - fy) * (1.f - fx) * vy0 * vx0;
                swt[1 * TP + p] = (1.f - fy) * fx * vy0 * vx1;
                swt[2 * TP + p] = fy * (1.f - fx) * vy1 * vx0;
                swt[3 * TP + p] = fy * fx * vy1 * vx1;

                int cy0 = min(max(y0, 0), HH - 1), cy1 = min(max(y1, 0), HH - 1);
                int cx0 = min(max(x0, 0), WW - 1), cx1 = min(max(x1, 0), WW - 1);
                sidx[0 * TP + p] = cy0 * WW + cx0;
                sidx[1 * TP + p] = cy0 * WW + cx1;
                sidx[2 * TP + p] = cy1 * WW + cx0;
                sidx[3 * TP + p] = cy1 * WW + cx1;
            }
            __syncthreads();
        }

        // ---- phase B: fill sv (sampled values) and wk (weights) ----
        {
            const float* wsrc = wgt + k * CC * O;
            for (int i = tid; i < CC * O; i += 256) wk[i] = wsrc[i];

            if (MODE > 0) {
                for (int e = tid; e < CC * TP; e += 256) {
                    int c = e >> 7;
                    int p = e & (TP - 1);
                    const float* xc = xb + c * HWS;
                    float v = swt[p]           * __ldg(xc + sidx[p])
                            + swt[TP + p]      * __ldg(xc + sidx[TP + p])
                            + swt[2 * TP + p]  * __ldg(xc + sidx[2 * TP + p])
                            + swt[3 * TP + p]  * __ldg(xc + sidx[3 * TP + p]);
                    sv[e] = v;
                }
            } else {
                int ky = k / 3 - 1, kx = k % 3 - 1;
                int y = h + ky;
                bool yok = (y >= 0 && y < HH);
                for (int e = tid; e < CC * TP; e += 256) {
                    int c = e >> 7;
                    int p = e & (TP - 1);
                    int x = p + kx;
                    float v = (yok && x >= 0 && x < WW) ? xb[c * HWS + y * WW + x] : 0.f;
                    sv[e] = v;
                }
            }
        }
        __syncthreads();

        // ---- GEMM: acc[pix][o] += sv[c][pix] * wk[c][o] ----
#pragma unroll 8
        for (int c = 0; c < CC; c++) {
            float4 wv = *(const float4*)(wk + c * O + ty * 4);
#pragma unroll
            for (int g = 0; g < NG; g++) {
                float4 a = *(const float4*)(sv + c * TP + g * (TX * 4) + tx * 4);
                acc[g][0].x += a.x * wv.x; acc[g][0].y += a.y * wv.x;
                acc[g][0].z += a.z * wv.x; acc[g][0].w += a.w * wv.x;
                acc[g][1].x += a.x * wv.y; acc[g][1].y += a.y * wv.y;
                acc[g][1].z += a.z * wv.y; acc[g][1].w += a.w * wv.y;
                acc[g][2].x += a.x * wv.z; acc[g][2].y += a.y * wv.z;
                acc[g][2].z += a.z * wv.z; acc[g][2].w += a.w * wv.z;
                acc[g][3].x += a.x * wv.w; acc[g][3].y += a.y * wv.w;
                acc[g][3].z += a.z * wv.w; acc[g][3].w += a.w * wv.w;
            }
        }
        __syncthreads();
    }

    // ---- epilogue ----
#pragma unroll
    for (int g = 0; g < NG; g++) {
        int p0 = g * (TX * 4) + tx * 4;
        float4 ga;
        if (MODE == 2) {
            float4 a4 = *(const float4*)(Aatt + b * HWS + sl + p0);
            float4 b4 = *(const float4*)(Batt + b * HWS + sl + p0);
            ga = make_float4((1.f - a4.x) * b4.x, (1.f - a4.y) * b4.y,
                             (1.f - a4.z) * b4.z, (1.f - a4.w) * b4.w);
        }
#pragma unroll
        for (int j = 0; j < 4; j++) {
            int o = ty * 4 + j;
            float4 v = acc[g][j];
            if (MODE == 0) {
                if (o < NOFF) {
                    float bb = bias[o];
                    v.x += bb; v.y += bb; v.z += bb; v.w += bb;
                    if (o >= 18) {
                        v.x = 1.f / (1.f + expf(-v.x));
                        v.y = 1.f / (1.f + expf(-v.y));
                        v.z = 1.f / (1.f + expf(-v.z));
                        v.w = 1.f / (1.f + expf(-v.w));
                    }
                    *(float4*)(out + (b * NOFF + o) * HWS + sl + p0) = v;
                }
            } else {
                float bb = bias[o];
                v.x = fmaxf(v.x + bb, 0.f);
                v.y = fmaxf(v.y + bb, 0.f);
                v.z = fmaxf(v.z + bb, 0.f);
                v.w = fmaxf(v.w + bb, 0.f);
                if (MODE == 2) {
                    v.x *= ga.x; v.y *= ga.y; v.z *= ga.z; v.w *= ga.w;
                }
                *(float4*)(out + (b * O + o) * HWS + sl + p0) = v;
            }
        }
    }
}

// ---------------- launch ----------------
extern "C" void kernel_launch(void* const* d_in, const int* in_sizes, int n_in,
                              void* d_out, int out_size)
{
    const float* pA   = (const float*)d_in[1];
    const float* pB   = (const float*)d_in[2];
    const float* Aatt = (const float*)d_in[3];
    const float* Batt = (const float*)d_in[4];
    const float* wo1  = (const float*)d_in[5];
    const float* bo1  = (const float*)d_in[6];
    const float* w1   = (const float*)d_in[7];
    const float* g1   = (const float*)d_in[8];
    const float* be1  = (const float*)d_in[9];
    const float* rm1  = (const float*)d_in[10];
    const float* rv1  = (const float*)d_in[11];
    const float* wo2  = (const float*)d_in[12];
    const float* bo2  = (const float*)d_in[13];
    const float* w2   = (const float*)d_in[14];
    const float* g2   = (const float*)d_in[15];
    const float* be2  = (const float*)d_in[16];
    const float* rm2  = (const float*)d_in[17];
    const float* rv2  = (const float*)d_in[18];

    float *x1, *x2, *off, *pwo1, *pwo2, *pwr1, *pwr2, *pb1, *pb2;
    cudaGetSymbolAddress((void**)&x1,   g_x1);
    cudaGetSymbolAddress((void**)&x2,   g_x2);
    cudaGetSymbolAddress((void**)&off,  g_off);
    cudaGetSymbolAddress((void**)&pwo1, g_wo1);
    cudaGetSymbolAddress((void**)&pwo2, g_wo2);
    cudaGetSymbolAddress((void**)&pwr1, g_wr1);
    cudaGetSymbolAddress((void**)&pwr2, g_wr2);
    cudaGetSymbolAddress((void**)&pb1,  g_b1);
    cudaGetSymbolAddress((void**)&pb2,  g_b2);

    // smem sizes: sv + wk (+ swt + sidx for deform)
    const int smem_off = (CC * TP + CC * 32) * 4;                    // 40960
    const int smem_d1  = (CC * TP + CC * O1 + 8 * TP) * 4;           // 53248
    const int smem_d2  = (CC * TP + CC * O2 + 8 * TP) * 4;           // 45056
    cudaFuncSetAttribute(gemm_kernel<32, 0>, cudaFuncAttributeMaxDynamicSharedMemorySize, smem_off);
    cudaFuncSetAttribute(gemm_kernel<O1, 1>, cudaFuncAttributeMaxDynamicSharedMemorySize, smem_d1);
    cudaFuncSetAttribute(gemm_kernel<O2, 2>, cudaFuncAttributeMaxDynamicSharedMemorySize, smem_d2);

    dim3 blk(256);
    dim3 grd(NPIX / TP);   // 512

    prep_kernel<<<256, 256>>>(pA, pB, wo1, w1, g1, be1, rm1, rv1,
                              wo2, w2, g2, be2, rm2, rv2);

    gemm_kernel<32, 0><<<grd, blk, smem_off>>>(x1, pwo1, bo1, off, nullptr, nullptr, nullptr);
    gemm_kernel<O1, 1><<<grd, blk, smem_d1>>>(x1, pwr1, pb1, x2, off, nullptr, nullptr);
    gemm_kernel<32, 0><<<grd, blk, smem_off>>>(x2, pwo2, bo2, off, nullptr, nullptr, nullptr);
    gemm_kernel<O2, 2><<<grd, blk, smem_d2>>>(x2, pwr2, pb2, (float*)d_out, off, Aatt, Batt);
}

// round 5
// speedup vs baseline: 2.4678x; 1.7912x over previous
#include <cuda_runtime.h>
#include <cuda_bf16.h>
#include <math.h>
#include <stdint.h>

#define BN 4
#define HH 128
#define WW 128
#define HWS (HH * WW)
#define CC 64
#define O1 64
#define O2 32
#define NOFF 27
#define NPIX (BN * HWS)
#define TP 128
#define ST 72              // smem row stride in bf16 elems (144B, 16B-granular)

// smem byte offsets
#define SM_AH   0
#define SM_AL   18432
#define SM_BH   36864
#define SM_BL   46080
#define SM_SWT  55296
#define SM_SIDX 57344
#define SM_TOTAL 59392

// ---------------- device scratch ----------------
__device__ float g_x1[BN * CC * HWS];
__device__ float g_x2[BN * CC * HWS];
__device__ float g_off[BN * NOFF * HWS];
// weights as bf16 hi/lo, layout [tap][n][c64] (k contiguous)
__device__ __nv_bfloat16 g_w1h[9 * O1 * CC];
__device__ __nv_bfloat16 g_w1l[9 * O1 * CC];
__device__ __nv_bfloat16 g_w2h[9 * O2 * CC];
__device__ __nv_bfloat16 g_w2l[9 * O2 * CC];
__device__ __nv_bfloat16 g_o1h[9 * O2 * CC];
__device__ __nv_bfloat16 g_o1l[9 * O2 * CC];
__device__ __nv_bfloat16 g_o2h[9 * O2 * CC];
__device__ __nv_bfloat16 g_o2l[9 * O2 * CC];
__device__ float g_b1[O1];
__device__ float g_b2[O2];

// ---------------- helpers ----------------
__device__ __forceinline__ unsigned smem_u32(const void* p) {
    unsigned a;
    asm("{ .reg .u64 t; cvta.to.shared.u64 t, %1; cvt.u32.u64 %0, t; }" : "=r"(a) : "l"(p));
    return a;
}
__device__ __forceinline__ void ldsm4(unsigned* r, unsigned addr) {
    asm volatile("ldmatrix.sync.aligned.m8n8.x4.shared.b16 {%0,%1,%2,%3}, [%4];"
                 : "=r"(r[0]), "=r"(r[1]), "=r"(r[2]), "=r"(r[3]) : "r"(addr));
}
__device__ __forceinline__ void mma16816(float* c, const unsigned* a, unsigned b0, unsigned b1) {
    asm volatile(
        "mma.sync.aligned.m16n8k16.row.col.f32.bf16.bf16.f32 "
        "{%0,%1,%2,%3}, {%4,%5,%6,%7}, {%8,%9}, {%0,%1,%2,%3};"
        : "+f"(c[0]), "+f"(c[1]), "+f"(c[2]), "+f"(c[3])
        : "r"(a[0]), "r"(a[1]), "r"(a[2]), "r"(a[3]), "r"(b0), "r"(b1));
}
__device__ __forceinline__ unsigned bf16x2_rn(float lo, float hi) {
    unsigned r;
    asm("cvt.rn.bf16x2.f32 %0, %1, %2;" : "=r"(r) : "f"(hi), "f"(lo));
    return r;
}

// ---------------- prep ----------------
__global__ void prep_kernel(
    const float* __restrict__ pA, const float* __restrict__ pB,
    const float* __restrict__ wo1,
    const float* __restrict__ w1, const float* __restrict__ g1,
    const float* __restrict__ be1, const float* __restrict__ rm1, const float* __restrict__ rv1,
    const float* __restrict__ wo2,
    const float* __restrict__ w2, const float* __restrict__ g2,
    const float* __restrict__ be2, const float* __restrict__ rm2, const float* __restrict__ rv2)
{
    int t = blockIdx.x * blockDim.x + threadIdx.x;
    int stride = gridDim.x * blockDim.x;

    for (int i = t; i < BN * CC * HWS; i += stride) {
        int b = i / (CC * HWS);
        int r = i % (CC * HWS);
        int c = r / HWS;
        int s = r % HWS;
        g_x1[i] = (c < 32) ? pB[(b * 32 + c) * HWS + s]
                           : pA[(b * 32 + (c - 32)) * HWS + s];
    }

    // main1: [k][o64][c64], BN-scaled, bf16 split
    for (int i = t; i < 9 * O1 * CC; i += stride) {
        int c = i & 63;
        int o = (i >> 6) & 63;
        int k = i >> 12;
        float inv = g1[o] * rsqrtf(rv1[o] + 1e-5f);
        float v = w1[(o * CC + c) * 9 + k] * inv;
        __nv_bfloat16 hb = __float2bfloat16(v);
        g_w1h[i] = hb;
        g_w1l[i] = __float2bfloat16(v - __bfloat162float(hb));
    }
    // main2: [k][o32][c64]
    for (int i = t; i < 9 * O2 * CC; i += stride) {
        int c = i & 63;
        int o = (i >> 6) & 31;
        int k = i >> 11;
        float inv = g2[o] * rsqrtf(rv2[o] + 1e-5f);
        float v = w2[(o * CC + c) * 9 + k] * inv;
        __nv_bfloat16 hb = __float2bfloat16(v);
        g_w2h[i] = hb;
        g_w2l[i] = __float2bfloat16(v - __bfloat162float(hb));
    }
    // offset convs: [k][o32 zero-pad>=27][c64]
    for (int i = t; i < 9 * O2 * CC; i += stride) {
        int c = i & 63;
        int o = (i >> 6) & 31;
        int k = i >> 11;
        float v1 = (o < NOFF) ? wo1[(o * CC + c) * 9 + k] : 0.f;
        float v2 = (o < NOFF) ? wo2[(o * CC + c) * 9 + k] : 0.f;
        __nv_bfloat16 h1 = __float2bfloat16(v1);
        __nv_bfloat16 h2 = __float2bfloat16(v2);
        g_o1h[i] = h1; g_o1l[i] = __float2bfloat16(v1 - __bfloat162float(h1));
        g_o2h[i] = h2; g_o2l[i] = __float2bfloat16(v2 - __bfloat162float(h2));
    }
    if (t < O1) { float inv = g1[t] * rsqrtf(rv1[t] + 1e-5f); g_b1[t] = be1[t] - rm1[t] * inv; }
    if (t < O2) { float inv = g2[t] * rsqrtf(rv2[t] + 1e-5f); g_b2[t] = be2[t] - rm2[t] * inv; }
}

// ---------------- fused conv via mma.sync bf16x3 ----------------
// MODE 0: offset conv (N=32; write 27 ch, +bias, sigmoid on 18..26)
// MODE 1: deform conv -> bias+relu
// MODE 2: deform conv -> bias+relu, *(1-Aatt)*Batt
template <int N, int MODE>
__global__ __launch_bounds__(256, 2)
void conv_mma_kernel(const float* __restrict__ xin,
                     const __nv_bfloat16* __restrict__ wh,
                     const __nv_bfloat16* __restrict__ wl,
                     const float* __restrict__ bias,
                     float* __restrict__ out,
                     const float* __restrict__ offs,
                     const float* __restrict__ Aatt,
                     const float* __restrict__ Batt)
{
    extern __shared__ __align__(16) char sm[];
    const unsigned sb = smem_u32(sm);

    const int tid = threadIdx.x;
    const int wid = tid >> 5;
    const int lid = tid & 31;

    const int b  = blockIdx.x >> 7;
    const int h  = blockIdx.x & 127;
    const int sl = h * WW;
    const float* xb = xin + b * CC * HWS;

    float* swt  = (float*)(sm + SM_SWT);
    int*   sidx = (int*)(sm + SM_SIDX);

    const int p  = tid & 127;           // staging pixel
    const int cb = (tid >> 7) * 32;     // staging channel half

    constexpr int NF16 = N / 16;
    float acc[N / 8][4];
#pragma unroll
    for (int i = 0; i < N / 8; i++)
#pragma unroll
        for (int j = 0; j < 4; j++) acc[i][j] = 0.f;

    // ldmatrix lane addresses (A and B), per warp
    const int lrow = lid & 15;
    const int lkof = (lid >> 4) * 8;
    const unsigned a_base = sb + ((wid * 16 + lrow) * ST + lkof) * 2;

#pragma unroll 1
    for (int k = 0; k < 9; k++) {
        // ---- phase A (deform): bilinear weights/indices ----
        if (MODE > 0) {
            if (tid < TP) {
                const float* op = offs + b * NOFF * HWS + sl + tid;
                float dy = op[(2 * k) * HWS];
                float dx = op[(2 * k + 1) * HWS];
                float m  = op[(18 + k) * HWS];       // pre-sigmoided

                float ys = (float)(h + (k / 3 - 1)) + dy;
                float xs = (float)(tid + (k % 3 - 1)) + dx;
                float y0f = floorf(ys), x0f = floorf(xs);
                float fy = ys - y0f, fx = xs - x0f;
                int y0 = (int)y0f, x0 = (int)x0f;
                int y1 = y0 + 1, x1 = x0 + 1;

                float vy0 = (y0 >= 0 && y0 < HH) ? m : 0.f;
                float vy1 = (y1 >= 0 && y1 < HH) ? m : 0.f;
                float vx0 = (x0 >= 0 && x0 < WW) ? 1.f : 0.f;
                float vx1 = (x1 >= 0 && x1 < WW) ? 1.f : 0.f;

                swt[0 * TP + tid] = (1.f - fy) * (1.f - fx) * vy0 * vx0;
                swt[1 * TP + tid] = (1.f - fy) * fx * vy0 * vx1;
                swt[2 * TP + tid] = fy * (1.f - fx) * vy1 * vx0;
                swt[3 * TP + tid] = fy * fx * vy1 * vx1;

                int cy0 = min(max(y0, 0), HH - 1), cy1 = min(max(y1, 0), HH - 1);
                int cx0 = min(max(x0, 0), WW - 1), cx1 = min(max(x1, 0), WW - 1);
                sidx[0 * TP + tid] = cy0 * WW + cx0;
                sidx[1 * TP + tid] = cy0 * WW + cx1;
                sidx[2 * TP + tid] = cy1 * WW + cx0;
                sidx[3 * TP + tid] = cy1 * WW + cx1;
            }
            __syncthreads();
        }

        // ---- stage A (hi/lo bf16) ----
        if (MODE > 0) {
            float w00 = swt[p], w01 = swt[TP + p], w10 = swt[2 * TP + p], w11 = swt[3 * TP + p];
            int i00 = sidx[p], i01 = sidx[TP + p], i10 = sidx[2 * TP + p], i11 = sidx[3 * TP + p];
            const float* xc = xb + cb * HWS;
#pragma unroll 4
            for (int j = 0; j < 16; j++) {
                const float* x0p = xc + (2 * j) * HWS;
                const float* x1p = x0p + HWS;
                float v0 = w00 * __ldg(x0p + i00) + w01 * __ldg(x0p + i01)
                         + w10 * __ldg(x0p + i10) + w11 * __ldg(x0p + i11);
                float v1 = w00 * __ldg(x1p + i00) + w01 * __ldg(x1p + i01)
                         + w10 * __ldg(x1p + i10) + w11 * __ldg(x1p + i11);
                unsigned hw = bf16x2_rn(v0, v1);
                float h0 = __uint_as_float(hw << 16);
                float h1 = __uint_as_float(hw & 0xFFFF0000u);
                unsigned lw = bf16x2_rn(v0 - h0, v1 - h1);
                unsigned boff = (unsigned)(p * ST + cb + 2 * j) * 2u;
                *(unsigned*)(sm + SM_AH + boff) = hw;
                *(unsigned*)(sm + SM_AL + boff) = lw;
            }
        } else {
            int ky = k / 3 - 1, kx = k % 3 - 1;
            int y = h + ky;
            int xcol = p + kx;
            bool ok = (y >= 0 && y < HH && xcol >= 0 && xcol < WW);
            const float* xrow = xb + cb * HWS + y * WW + xcol;
#pragma unroll 4
            for (int j = 0; j < 16; j++) {
                float v0 = ok ? __ldg(xrow + (2 * j) * HWS) : 0.f;
                float v1 = ok ? __ldg(xrow + (2 * j + 1) * HWS) : 0.f;
                unsigned hw = bf16x2_rn(v0, v1);
                float h0 = __uint_as_float(hw << 16);
                float h1 = __uint_as_float(hw & 0xFFFF0000u);
                unsigned lw = bf16x2_rn(v0 - h0, v1 - h1);
                unsigned boff = (unsigned)(p * ST + cb + 2 * j) * 2u;
                *(unsigned*)(sm + SM_AH + boff) = hw;
                *(unsigned*)(sm + SM_AL + boff) = lw;
            }
        }

        // ---- stage B (copy [n][c64] -> smem stride ST) ----
        {
            const unsigned* shp = (const unsigned*)(wh + k * (N * CC));
            const unsigned* slp = (const unsigned*)(wl + k * (N * CC));
            for (int i = tid; i < N * 32; i += 256) {
                int n = i >> 5, kw = i & 31;
                ((unsigned*)(sm + SM_BH))[n * (ST / 2) + kw] = __ldg(shp + i);
                ((unsigned*)(sm + SM_BL))[n * (ST / 2) + kw] = __ldg(slp + i);
            }
        }
        __syncthreads();

        // ---- MMA over 4 k-steps ----
#pragma unroll
        for (int q = 0; q < 4; q++) {
            unsigned ah[4], al[4];
            ldsm4(ah, a_base + (SM_AH) + q * 32);   // q*16 bf16 = 32B
            ldsm4(al, a_base + (SM_AL) + q * 32);
#pragma unroll
            for (int nf = 0; nf < NF16; nf++) {
                unsigned bh[4], bl[4];
                unsigned b_base = sb + ((nf * 16 + lrow) * ST + q * 16 + lkof) * 2;
                ldsm4(bh, b_base + SM_BH);
                ldsm4(bl, b_base + SM_BL);
                // n-slice lo (n0-7): {r0,r2}; hi (n8-15): {r1,r3}
                mma16816(acc[nf * 2],     ah, bh[0], bh[2]);
                mma16816(acc[nf * 2 + 1], ah, bh[1], bh[3]);
                mma16816(acc[nf * 2],     ah, bl[0], bl[2]);
                mma16816(acc[nf * 2 + 1], ah, bl[1], bl[3]);
                mma16816(acc[nf * 2],     al, bh[0], bh[2]);
                mma16816(acc[nf * 2 + 1], al, bh[1], bh[3]);
            }
        }
        __syncthreads();
    }

    // ---- epilogue ----
    const int gm = lid >> 2;
    const int gn = (lid & 3) * 2;
    const int px0 = wid * 16 + gm;
    const int px1 = px0 + 8;
    const int g0 = sl + px0;
    const int g1i = sl + px1;

    float ga0 = 1.f, ga1 = 1.f;
    if (MODE == 2) {
        ga0 = (1.f - __ldg(Aatt + b * HWS + g0)) * __ldg(Batt + b * HWS + g0);
        ga1 = (1.f - __ldg(Aatt + b * HWS + g1i)) * __ldg(Batt + b * HWS + g1i);
    }

#pragma unroll
    for (int nf = 0; nf < N / 8; nf++) {
        int o = nf * 8 + gn;
#pragma unroll
        for (int e = 0; e < 2; e++) {
            int oo = o + e;
            float v0 = acc[nf][e];
            float v1 = acc[nf][e + 2];
            if (MODE == 0) {
                if (oo < NOFF) {
                    float bb = __ldg(bias + oo);
                    v0 += bb; v1 += bb;
                    if (oo >= 18) {
                        v0 = 1.f / (1.f + expf(-v0));
                        v1 = 1.f / (1.f + expf(-v1));
                    }
                    out[(b * NOFF + oo) * HWS + g0]  = v0;
                    out[(b * NOFF + oo) * HWS + g1i] = v1;
                }
            } else {
                float bb = __ldg(bias + oo);
                v0 = fmaxf(v0 + bb, 0.f);
                v1 = fmaxf(v1 + bb, 0.f);
                if (MODE == 2) { v0 *= ga0; v1 *= ga1; }
                out[(b * N + oo) * HWS + g0]  = v0;
                out[(b * N + oo) * HWS + g1i] = v1;
            }
        }
    }
}

// ---------------- launch ----------------
extern "C" void kernel_launch(void* const* d_in, const int* in_sizes, int n_in,
                              void* d_out, int out_size)
{
    const float* pA   = (const float*)d_in[1];
    const float* pB   = (const float*)d_in[2];
    const float* Aatt = (const float*)d_in[3];
    const float* Batt = (const float*)d_in[4];
    const float* wo1  = (const float*)d_in[5];
    const float* bo1  = (const float*)d_in[6];
    const float* w1   = (const float*)d_in[7];
    const float* g1   = (const float*)d_in[8];
    const float* be1  = (const float*)d_in[9];
    const float* rm1  = (const float*)d_in[10];
    const float* rv1  = (const float*)d_in[11];
    const float* wo2  = (const float*)d_in[12];
    const float* bo2  = (const float*)d_in[13];
    const float* w2   = (const float*)d_in[14];
    const float* g2   = (const float*)d_in[15];
    const float* be2  = (const float*)d_in[16];
    const float* rm2  = (const float*)d_in[17];
    const float* rv2  = (const float*)d_in[18];

    float *x1, *x2, *off, *pb1, *pb2;
    __nv_bfloat16 *w1h, *w1l, *w2h, *w2l, *o1h, *o1l, *o2h, *o2l;
    cudaGetSymbolAddress((void**)&x1,  g_x1);
    cudaGetSymbolAddress((void**)&x2,  g_x2);
    cudaGetSymbolAddress((void**)&off, g_off);
    cudaGetSymbolAddress((void**)&pb1, g_b1);
    cudaGetSymbolAddress((void**)&pb2, g_b2);
    cudaGetSymbolAddress((void**)&w1h, g_w1h);
    cudaGetSymbolAddress((void**)&w1l, g_w1l);
    cudaGetSymbolAddress((void**)&w2h, g_w2h);
    cudaGetSymbolAddress((void**)&w2l, g_w2l);
    cudaGetSymbolAddress((void**)&o1h, g_o1h);
    cudaGetSymbolAddress((void**)&o1l, g_o1l);
    cudaGetSymbolAddress((void**)&o2h, g_o2h);
    cudaGetSymbolAddress((void**)&o2l, g_o2l);

    cudaFuncSetAttribute(conv_mma_kernel<32, 0>, cudaFuncAttributeMaxDynamicSharedMemorySize, SM_TOTAL);
    cudaFuncSetAttribute(conv_mma_kernel<64, 1>, cudaFuncAttributeMaxDynamicSharedMemorySize, SM_TOTAL);
    cudaFuncSetAttribute(conv_mma_kernel<32, 2>, cudaFuncAttributeMaxDynamicSharedMemorySize, SM_TOTAL);

    dim3 blk(256);
    dim3 grd(NPIX / TP);   // 512

    prep_kernel<<<256, 256>>>(pA, pB, wo1, w1, g1, be1, rm1, rv1,
                              wo2, w2, g2, be2, rm2, rv2);

    conv_mma_kernel<32, 0><<<grd, blk, SM_TOTAL>>>(x1, o1h, o1l, bo1, off, nullptr, nullptr, nullptr);
    conv_mma_kernel<64, 1><<<grd, blk, SM_TOTAL>>>(x1, w1h, w1l, pb1, x2, off, nullptr, nullptr);
    conv_mma_kernel<32, 0><<<grd, blk, SM_TOTAL>>>(x2, o2h, o2l, bo2, off, nullptr, nullptr, nullptr);
    conv_mma_kernel<32, 2><<<grd, blk, SM_TOTAL>>>(x2, w2h, w2l, pb2, (float*)d_out, off, Aatt, Batt);
}